// round 13
// baseline (speedup 1.0000x reference)
#include <cuda_runtime.h>
#include <cuda_fp16.h>
#include <cstdint>

#define Bn  256
#define Vn  2048
#define PDn 1024
#define MDn 512
#define Hn  512
#define W1LD (PDn + MDn)

#define GTP 40   // GEMM smem row stride (halves)
#define HPP 520  // score hp row stride (halves)

// Intermediates (device globals; no allocations).
__device__ __half g_hm[Vn * Hn];          // [v][h]
__device__ __half g_hp2[2 * Bn * Hn];     // split-K2 slices, [b][h]; b1 in slice 0

__device__ __forceinline__ unsigned tanh2_f16(unsigned x) {
    unsigned y;
    asm("tanh.approx.f16x2 %0, %1;" : "=r"(y) : "r"(x));
    return y;
}
__device__ __forceinline__ unsigned hadd2u(unsigned a, unsigned b) {
    unsigned d;
    asm("add.rn.f16x2 %0, %1, %2;" : "=r"(d) : "r"(a), "r"(b));
    return d;
}

// tanh on the FMA pipe (R10-proven): 12 f16x2 ops, no cvt/mov/div.
__device__ __forceinline__ unsigned tanh2_fma(unsigned xu) {
    __half2 x = *(__half2*)&xu;
    __half2 xc = __hmin2(__hmax2(x, __float2half2_rn(-2.75f)),
                         __float2half2_rn(2.75f));
    __half2 u = __hmul2(xc, xc);
    __half2 s = __hfma2(u, __float2half2_rn(0.26446280f),
                           __float2half2_rn(-1.0f));
    __half2 p = __hfma2(__float2half2_rn(-0.0224000f), s,
                        __float2half2_rn( 0.0371840f));
    p = __hfma2(p, s, __float2half2_rn(-0.0164160f));
    p = __hfma2(p, s, __float2half2_rn( 0.0272720f));
    p = __hfma2(p, s, __float2half2_rn(-0.0733200f));
    p = __hfma2(p, s, __float2half2_rn( 0.1221940f));
    p = __hfma2(p, s, __float2half2_rn(-0.2074220f));
    p = __hfma2(p, s, __float2half2_rn( 0.4935290f));
    __half2 y = __hmul2(xc, p);
    return *(unsigned*)&y;
}

__device__ __forceinline__ void mma_16816(float c[4],
    unsigned a0, unsigned a1, unsigned a2, unsigned a3,
    unsigned b0, unsigned b1)
{
    asm volatile(
        "mma.sync.aligned.m16n8k16.row.col.f32.f16.f16.f32 "
        "{%0,%1,%2,%3}, {%4,%5,%6,%7}, {%8,%9}, {%0,%1,%2,%3};"
        : "+f"(c[0]), "+f"(c[1]), "+f"(c[2]), "+f"(c[3])
        : "r"(a0), "r"(a1), "r"(a2), "r"(a3), "r"(b0), "r"(b1));
}
__device__ __forceinline__ void ldsm_x4(unsigned& r0, unsigned& r1,
                                        unsigned& r2, unsigned& r3,
                                        unsigned addr) {
    asm volatile("ldmatrix.sync.aligned.m8n8.x4.shared.b16 {%0,%1,%2,%3}, [%4];"
        : "=r"(r0), "=r"(r1), "=r"(r2), "=r"(r3) : "r"(addr));
}
__device__ __forceinline__ void cp_async16(unsigned smem, const void* gptr) {
    asm volatile("cp.async.cg.shared.global [%0], [%1], 16;"
        :: "r"(smem), "l"(gptr) : "memory");
}

// ---------------------------------------------------------------------------
// HMMA GEMM (R11 verbatim, measured ~10.7us). 80 blocks x 256 thr,
// tile 128m x 128h, K=512; ldmatrix fragments; double-buffered smem.
// ---------------------------------------------------------------------------
__global__ void __launch_bounds__(256) hmma_gemm_kernel(
    const float* __restrict__ patient,
    const float* __restrict__ atc4,
    const float* __restrict__ W1,
    const float* __restrict__ b1)
{
    __shared__ __half As[2][128 * GTP];
    __shared__ __half Ws[2][128 * GTP];

    const int bid = blockIdx.x;
    const int tid = threadIdx.x;

    const float* A;
    __half* dst;
    int LDA, m0, n0, kA0, kW0;
    bool add_b1;

    if (bid < 64) {                   // hm
        A = atc4;  LDA = MDn;  dst = g_hm;
        m0 = (bid & 15) * 128;
        n0 = (bid >> 4) * 128;
        kA0 = 0;  kW0 = PDn;
        add_b1 = false;
    } else {                          // hp split-K2
        int t = bid - 64;
        int s = t & 1;
        A = patient;  LDA = PDn;  dst = g_hp2 + s * (Bn * Hn);
        m0 = ((t >> 1) & 1) * 128;
        n0 = (t >> 2) * 128;
        kA0 = s * 512;  kW0 = s * 512;
        add_b1 = (s == 0);
    }

    const int wid = tid >> 5, lane = tid & 31;
    const int g = lane >> 2, t4 = lane & 3;
    const int wm = wid & 1, wn = wid >> 1;

    const int lrow = lane & 7;
    const int grp  = lane >> 3;
    const int baseA_h = (wm * 64 + lrow + (grp & 1) * 8) * GTP + (grp >> 1) * 8;
    const int baseB_h = (wn * 32 + lrow + (grp >> 1) * 8) * GTP + (grp & 1) * 8;

    const unsigned asU = (unsigned)__cvta_generic_to_shared(&As[0][0]);
    const unsigned wsU = (unsigned)__cvta_generic_to_shared(&Ws[0][0]);
    const unsigned bufStride = 128 * GTP * 2;

    float acc[4][4][4];
    #pragma unroll
    for (int i = 0; i < 4; i++)
        #pragma unroll
        for (int j = 0; j < 4; j++)
            #pragma unroll
            for (int c = 0; c < 4; c++) acc[i][j][c] = 0.0f;

    const int sr = tid >> 3;
    const int sq = tid & 7;

    float4 fA[4], fW[4];
    auto ldg = [&](int ch) {
        int k0 = ch * 32;
        #pragma unroll
        for (int it = 0; it < 4; it++) {
            int r = sr + it * 32;
            fA[it] = *(const float4*)(A  + (size_t)(m0 + r) * LDA  + kA0 + k0 + sq * 4);
            fW[it] = *(const float4*)(W1 + (size_t)(n0 + r) * W1LD + kW0 + k0 + sq * 4);
        }
    };
    auto sts = [&](int buf) {
        #pragma unroll
        for (int it = 0; it < 4; it++) {
            int r = sr + it * 32;
            __half ha[4] = { __float2half_rn(fA[it].x), __float2half_rn(fA[it].y),
                             __float2half_rn(fA[it].z), __float2half_rn(fA[it].w) };
            __half hw[4] = { __float2half_rn(fW[it].x), __float2half_rn(fW[it].y),
                             __float2half_rn(fW[it].z), __float2half_rn(fW[it].w) };
            *(uint2*)&As[buf][r * GTP + sq * 4] = *(uint2*)ha;
            *(uint2*)&Ws[buf][r * GTP + sq * 4] = *(uint2*)hw;
        }
    };

    const int NCH = 512 / 32;
    ldg(0);
    sts(0);
    ldg(1);
    __syncthreads();

    for (int c = 0; c < NCH; c++) {
        const int cur = c & 1;
        if (c + 1 < NCH) {
            sts(cur ^ 1);
            if (c + 2 < NCH) ldg(c + 2);
        }

        const unsigned aBase = asU + cur * bufStride + baseA_h * 2;
        const unsigned bBase = wsU + cur * bufStride + baseB_h * 2;

        #pragma unroll
        for (int ks = 0; ks < 2; ks++) {
            const int kOff = ks * 16 * 2;
            unsigned a[4][4], b[4][2];
            #pragma unroll
            for (int mi = 0; mi < 4; mi++)
                ldsm_x4(a[mi][0], a[mi][1], a[mi][2], a[mi][3],
                        aBase + mi * (16 * GTP * 2) + kOff);
            ldsm_x4(b[0][0], b[0][1], b[1][0], b[1][1], bBase + kOff);
            ldsm_x4(b[2][0], b[2][1], b[3][0], b[3][1],
                    bBase + 16 * GTP * 2 + kOff);
            #pragma unroll
            for (int mi = 0; mi < 4; mi++)
                #pragma unroll
                for (int j = 0; j < 4; j++)
                    mma_16816(acc[mi][j], a[mi][0], a[mi][1], a[mi][2], a[mi][3],
                              b[j][0], b[j][1]);
        }
        __syncthreads();
    }

    #pragma unroll
    for (int mi = 0; mi < 4; mi++) {
        int r0 = m0 + wm * 64 + mi * 16 + g, r1 = r0 + 8;
        #pragma unroll
        for (int j = 0; j < 4; j++) {
            int cn = n0 + wn * 32 + j * 8 + 2 * t4;
            float x0 = acc[mi][j][0], x1 = acc[mi][j][1];
            float x2 = acc[mi][j][2], x3 = acc[mi][j][3];
            if (add_b1) {
                float2 bb = *(const float2*)&b1[cn];
                x0 += bb.x; x1 += bb.y; x2 += bb.x; x3 += bb.y;
            }
            *(__half2*)&dst[(size_t)r0 * Hn + cn] = __floats2half2_rn(x0, x1);
            *(__half2*)&dst[(size_t)r1 * Hn + cn] = __floats2half2_rn(x2, x3);
        }
    }
}

// ---------------------------------------------------------------------------
// Score (R12 pipeline, doubled tile): 128v x 8b per block, 256 thr (8 warps),
// 512 blocks, all co-resident (4/SM). hp staged once per block; hm via
// cp.async double buffer. Hybrid tanh rebalanced to 11/32 on the FMA pipe.
// ---------------------------------------------------------------------------
__global__ void __launch_bounds__(256, 4) score_kernel(
    const float* __restrict__ w2, const float* __restrict__ b2p,
    float* __restrict__ out)
{
    __shared__ __half hm_sh[2][128 * 72];  // 36.9 KB double buffer
    __shared__ __half hp_sh[8 * HPP];      // 8.3 KB, full H per b
    __shared__ __half w2h_sh[Hn];

    const int tid  = threadIdx.x;
    const int v0   = blockIdx.x * 128;
    const int b0   = blockIdx.y * 8;
    const int lane = tid & 31;
    const int g    = lane >> 2;
    const int t    = lane & 3;
    const int vbase = (tid >> 5) * 16;     // 8 warps x 16v = 128v

    if (tid < 128) {   // w2 -> fp16 once
        float4 w = ((const float4*)w2)[tid];
        __half h4[4] = { __float2half_rn(w.x), __float2half_rn(w.y),
                         __float2half_rn(w.z), __float2half_rn(w.w) };
        *(uint2*)&w2h_sh[tid * 4] = *(uint2*)h4;
    }
    // hp full-H staging: 8b x 512h, slice0+slice1 (b1 pre-folded in slice 0).
    #pragma unroll
    for (int r = 0; r < 2; r++) {
        int idx = tid + r * 256;       // 0..511
        int b = idx >> 6, q = idx & 63;
        size_t off = (size_t)(b0 + b) * Hn + q * 8;
        uint4 x = *(const uint4*)(g_hp2 + off);
        uint4 y = *(const uint4*)(g_hp2 + Bn * Hn + off);
        uint4 z;
        z.x = hadd2u(x.x, y.x);  z.y = hadd2u(x.y, y.y);
        z.z = hadd2u(x.z, y.z);  z.w = hadd2u(x.w, y.w);
        *(uint4*)&hp_sh[b * HPP + q * 8] = z;
    }

    // cp.async staging: 128v x 64h per chunk = 1024 x 16B, 4 per thread.
    const unsigned hmU = (unsigned)__cvta_generic_to_shared(&hm_sh[0][0]);
    const unsigned hmBuf = 128 * 72 * 2;   // bytes per buffer
    const int svv = tid >> 3;              // v row 0..31 (+32 per r)
    const int sq8 = (tid & 7) * 8;         // h col (halves)

    auto stage_hm = [&](int ch) {
        int buf = ch & 1;
        int h0 = ch * 64;
        #pragma unroll
        for (int r = 0; r < 4; r++) {
            int vv = svv + r * 32;
            cp_async16(hmU + buf * hmBuf + (vv * 72 + sq8) * 2,
                       g_hm + (size_t)(v0 + vv) * Hn + h0 + sq8);
        }
        asm volatile("cp.async.commit_group;" ::: "memory");
    };

    float acc[8][4];
    #pragma unroll
    for (int b = 0; b < 8; b++)
        #pragma unroll
        for (int c = 0; c < 4; c++) acc[b][c] = 0.0f;

    stage_hm(0);
    stage_hm(1);

    for (int ch = 0; ch < 8; ch++) {
        if (ch < 7)
            asm volatile("cp.async.wait_group 1;" ::: "memory");
        else
            asm volatile("cp.async.wait_group 0;" ::: "memory");
        __syncthreads();

        const __half* hmb = hm_sh[ch & 1];
        const __half* hmr0 = &hmb[(vbase + g) * 72];
        const __half* hmr1 = &hmb[(vbase + g + 8) * 72];
        const int h0 = ch * 64;

        #pragma unroll
        for (int c = 0; c < 4; c++) {
            const int hb = c * 16;
            unsigned m00 = *(const unsigned*)&hmr0[hb + 2 * t];
            unsigned m10 = *(const unsigned*)&hmr1[hb + 2 * t];
            unsigned m01 = *(const unsigned*)&hmr0[hb + 2 * t + 8];
            unsigned m11 = *(const unsigned*)&hmr1[hb + 2 * t + 8];
            unsigned bw0 = *(const unsigned*)&w2h_sh[h0 + hb + 2 * t];
            unsigned bw1 = *(const unsigned*)&w2h_sh[h0 + hb + 2 * t + 8];
            #pragma unroll
            for (int b = 0; b < 8; b++) {
                const __half* hpr = &hp_sh[b * HPP + h0 + hb];
                unsigned p0 = *(const unsigned*)&hpr[2 * t];
                unsigned p1 = *(const unsigned*)&hpr[2 * t + 8];
                unsigned x0 = hadd2u(m00, p0);
                unsigned x1 = hadd2u(m10, p0);
                unsigned x2 = hadd2u(m01, p1);
                unsigned x3 = hadd2u(m11, p1);
                // Routing 11/32 on FMA pipe (a1 always; a3 for b<3).
                unsigned a0 = tanh2_f16(x0);
                unsigned a1 = tanh2_fma(x1);
                unsigned a2 = tanh2_f16(x2);
                unsigned a3 = (b < 3) ? tanh2_fma(x3) : tanh2_f16(x3);
                mma_16816(acc[b], a0, a1, a2, a3, bw0, bw1);
            }
        }
        __syncthreads();
        if (ch + 2 < 8) stage_hm(ch + 2);
    }

    const float b2 = *b2p;
    if (t == 0) {
        #pragma unroll
        for (int b = 0; b < 8; b++) {
            out[(size_t)(b0 + b) * Vn + v0 + vbase + g]     = acc[b][0] + b2;
            out[(size_t)(b0 + b) * Vn + v0 + vbase + g + 8] = acc[b][2] + b2;
        }
    }
}

extern "C" void kernel_launch(void* const* d_in, const int* in_sizes, int n_in,
                              void* d_out, int out_size) {
    const float* patient = (const float*)d_in[0];  // [B, PD]
    const float* atc4    = (const float*)d_in[1];  // [V, MD]
    const float* W1      = (const float*)d_in[2];  // [H, PD+MD]
    const float* b1      = (const float*)d_in[3];  // [H]
    const float* w2      = (const float*)d_in[4];  // [H]
    const float* b2      = (const float*)d_in[5];  // scalar
    float* out = (float*)d_out;                    // [B, V]

    hmma_gemm_kernel<<<80, 256>>>(patient, atc4, W1, b1);

    dim3 grid(Vn / 128, Bn / 8);   // 16 x 32 = 512 blocks
    score_kernel<<<grid, 256>>>(w2, b2, out);
}

// round 14
// speedup vs baseline: 1.0938x; 1.0938x over previous
#include <cuda_runtime.h>
#include <cuda_fp16.h>
#include <cstdint>

#define Bn  256
#define Vn  2048
#define PDn 1024
#define MDn 512
#define Hn  512
#define W1LD (PDn + MDn)

#define GTP 40   // GEMM smem row stride (halves)
#define HPP 520  // score hp row stride (halves)

// Intermediates (device globals; no allocations).
__device__ __half g_hm[Vn * Hn];          // [v][h]
__device__ __half g_hp2[2 * Bn * Hn];     // split-K2 slices, [b][h]; b1 in slice 0

__device__ __forceinline__ unsigned tanh2_f16(unsigned x) {
    unsigned y;
    asm("tanh.approx.f16x2 %0, %1;" : "=r"(y) : "r"(x));
    return y;
}
__device__ __forceinline__ unsigned hadd2u(unsigned a, unsigned b) {
    unsigned d;
    asm("add.rn.f16x2 %0, %1, %2;" : "=r"(d) : "r"(a), "r"(b));
    return d;
}

// tanh on the FMA pipe (R10-proven): 12 f16x2 ops, no cvt/mov/div.
__device__ __forceinline__ unsigned tanh2_fma(unsigned xu) {
    __half2 x = *(__half2*)&xu;
    __half2 xc = __hmin2(__hmax2(x, __float2half2_rn(-2.75f)),
                         __float2half2_rn(2.75f));
    __half2 u = __hmul2(xc, xc);
    __half2 s = __hfma2(u, __float2half2_rn(0.26446280f),
                           __float2half2_rn(-1.0f));
    __half2 p = __hfma2(__float2half2_rn(-0.0224000f), s,
                        __float2half2_rn( 0.0371840f));
    p = __hfma2(p, s, __float2half2_rn(-0.0164160f));
    p = __hfma2(p, s, __float2half2_rn( 0.0272720f));
    p = __hfma2(p, s, __float2half2_rn(-0.0733200f));
    p = __hfma2(p, s, __float2half2_rn( 0.1221940f));
    p = __hfma2(p, s, __float2half2_rn(-0.2074220f));
    p = __hfma2(p, s, __float2half2_rn( 0.4935290f));
    __half2 y = __hmul2(xc, p);
    return *(unsigned*)&y;
}

__device__ __forceinline__ void mma_16816(float c[4],
    unsigned a0, unsigned a1, unsigned a2, unsigned a3,
    unsigned b0, unsigned b1)
{
    asm volatile(
        "mma.sync.aligned.m16n8k16.row.col.f32.f16.f16.f32 "
        "{%0,%1,%2,%3}, {%4,%5,%6,%7}, {%8,%9}, {%0,%1,%2,%3};"
        : "+f"(c[0]), "+f"(c[1]), "+f"(c[2]), "+f"(c[3])
        : "r"(a0), "r"(a1), "r"(a2), "r"(a3), "r"(b0), "r"(b1));
}
__device__ __forceinline__ void ldsm_x4(unsigned& r0, unsigned& r1,
                                        unsigned& r2, unsigned& r3,
                                        unsigned addr) {
    asm volatile("ldmatrix.sync.aligned.m8n8.x4.shared.b16 {%0,%1,%2,%3}, [%4];"
        : "=r"(r0), "=r"(r1), "=r"(r2), "=r"(r3) : "r"(addr));
}
__device__ __forceinline__ void cp_async16(unsigned smem, const void* gptr) {
    asm volatile("cp.async.cg.shared.global [%0], [%1], 16;"
        :: "r"(smem), "l"(gptr) : "memory");
}

// ---------------------------------------------------------------------------
// HMMA GEMM (R11 verbatim, measured ~10.7us). 80 blocks x 256 thr,
// tile 128m x 128h, K=512; ldmatrix fragments; double-buffered smem.
// ---------------------------------------------------------------------------
__global__ void __launch_bounds__(256) hmma_gemm_kernel(
    const float* __restrict__ patient,
    const float* __restrict__ atc4,
    const float* __restrict__ W1,
    const float* __restrict__ b1)
{
    __shared__ __half As[2][128 * GTP];
    __shared__ __half Ws[2][128 * GTP];

    const int bid = blockIdx.x;
    const int tid = threadIdx.x;

    const float* A;
    __half* dst;
    int LDA, m0, n0, kA0, kW0;
    bool add_b1;

    if (bid < 64) {                   // hm
        A = atc4;  LDA = MDn;  dst = g_hm;
        m0 = (bid & 15) * 128;
        n0 = (bid >> 4) * 128;
        kA0 = 0;  kW0 = PDn;
        add_b1 = false;
    } else {                          // hp split-K2
        int t = bid - 64;
        int s = t & 1;
        A = patient;  LDA = PDn;  dst = g_hp2 + s * (Bn * Hn);
        m0 = ((t >> 1) & 1) * 128;
        n0 = (t >> 2) * 128;
        kA0 = s * 512;  kW0 = s * 512;
        add_b1 = (s == 0);
    }

    const int wid = tid >> 5, lane = tid & 31;
    const int g = lane >> 2, t4 = lane & 3;
    const int wm = wid & 1, wn = wid >> 1;

    const int lrow = lane & 7;
    const int grp  = lane >> 3;
    const int baseA_h = (wm * 64 + lrow + (grp & 1) * 8) * GTP + (grp >> 1) * 8;
    const int baseB_h = (wn * 32 + lrow + (grp >> 1) * 8) * GTP + (grp & 1) * 8;

    const unsigned asU = (unsigned)__cvta_generic_to_shared(&As[0][0]);
    const unsigned wsU = (unsigned)__cvta_generic_to_shared(&Ws[0][0]);
    const unsigned bufStride = 128 * GTP * 2;

    float acc[4][4][4];
    #pragma unroll
    for (int i = 0; i < 4; i++)
        #pragma unroll
        for (int j = 0; j < 4; j++)
            #pragma unroll
            for (int c = 0; c < 4; c++) acc[i][j][c] = 0.0f;

    const int sr = tid >> 3;
    const int sq = tid & 7;

    float4 fA[4], fW[4];
    auto ldg = [&](int ch) {
        int k0 = ch * 32;
        #pragma unroll
        for (int it = 0; it < 4; it++) {
            int r = sr + it * 32;
            fA[it] = *(const float4*)(A  + (size_t)(m0 + r) * LDA  + kA0 + k0 + sq * 4);
            fW[it] = *(const float4*)(W1 + (size_t)(n0 + r) * W1LD + kW0 + k0 + sq * 4);
        }
    };
    auto sts = [&](int buf) {
        #pragma unroll
        for (int it = 0; it < 4; it++) {
            int r = sr + it * 32;
            __half ha[4] = { __float2half_rn(fA[it].x), __float2half_rn(fA[it].y),
                             __float2half_rn(fA[it].z), __float2half_rn(fA[it].w) };
            __half hw[4] = { __float2half_rn(fW[it].x), __float2half_rn(fW[it].y),
                             __float2half_rn(fW[it].z), __float2half_rn(fW[it].w) };
            *(uint2*)&As[buf][r * GTP + sq * 4] = *(uint2*)ha;
            *(uint2*)&Ws[buf][r * GTP + sq * 4] = *(uint2*)hw;
        }
    };

    const int NCH = 512 / 32;
    ldg(0);
    sts(0);
    ldg(1);
    __syncthreads();

    for (int c = 0; c < NCH; c++) {
        const int cur = c & 1;
        if (c + 1 < NCH) {
            sts(cur ^ 1);
            if (c + 2 < NCH) ldg(c + 2);
        }

        const unsigned aBase = asU + cur * bufStride + baseA_h * 2;
        const unsigned bBase = wsU + cur * bufStride + baseB_h * 2;

        #pragma unroll
        for (int ks = 0; ks < 2; ks++) {
            const int kOff = ks * 16 * 2;
            unsigned a[4][4], b[4][2];
            #pragma unroll
            for (int mi = 0; mi < 4; mi++)
                ldsm_x4(a[mi][0], a[mi][1], a[mi][2], a[mi][3],
                        aBase + mi * (16 * GTP * 2) + kOff);
            ldsm_x4(b[0][0], b[0][1], b[1][0], b[1][1], bBase + kOff);
            ldsm_x4(b[2][0], b[2][1], b[3][0], b[3][1],
                    bBase + 16 * GTP * 2 + kOff);
            #pragma unroll
            for (int mi = 0; mi < 4; mi++)
                #pragma unroll
                for (int j = 0; j < 4; j++)
                    mma_16816(acc[mi][j], a[mi][0], a[mi][1], a[mi][2], a[mi][3],
                              b[j][0], b[j][1]);
        }
        __syncthreads();
    }

    #pragma unroll
    for (int mi = 0; mi < 4; mi++) {
        int r0 = m0 + wm * 64 + mi * 16 + g, r1 = r0 + 8;
        #pragma unroll
        for (int j = 0; j < 4; j++) {
            int cn = n0 + wn * 32 + j * 8 + 2 * t4;
            float x0 = acc[mi][j][0], x1 = acc[mi][j][1];
            float x2 = acc[mi][j][2], x3 = acc[mi][j][3];
            if (add_b1) {
                float2 bb = *(const float2*)&b1[cn];
                x0 += bb.x; x1 += bb.y; x2 += bb.x; x3 += bb.y;
            }
            *(__half2*)&dst[(size_t)r0 * Hn + cn] = __floats2half2_rn(x0, x1);
            *(__half2*)&dst[(size_t)r1 * Hn + cn] = __floats2half2_rn(x2, x3);
        }
    }
}

// ---------------------------------------------------------------------------
// Score (R12 structure verbatim, measured 56.9us; ONLY change: tanh routing
// 12/32 -> 11/32 on the FMA pipe, matching the calibrated balance point
// alpha* = 0.35). 64v x 8b tile, 128 thr, grid 1024, 8 blocks/SM.
// hp staged once for all H; hm via cp.async double buffer.
// ---------------------------------------------------------------------------
__global__ void __launch_bounds__(128, 8) score_kernel(
    const float* __restrict__ w2, const float* __restrict__ b2p,
    float* __restrict__ out)
{
    __shared__ __half hm_sh[2][64 * 72];  // 18.4 KB double buffer
    __shared__ __half hp_sh[8 * HPP];     // 8.3 KB, full H per b
    __shared__ __half w2h_sh[Hn];

    const int tid  = threadIdx.x;
    const int v0   = blockIdx.x * 64;
    const int b0   = blockIdx.y * 8;
    const int lane = tid & 31;
    const int g    = lane >> 2;
    const int t    = lane & 3;
    const int vbase = (tid >> 5) * 16;

    {   // w2 -> fp16 once
        float4 w = ((const float4*)w2)[tid];
        __half h4[4] = { __float2half_rn(w.x), __float2half_rn(w.y),
                         __float2half_rn(w.z), __float2half_rn(w.w) };
        *(uint2*)&w2h_sh[tid * 4] = *(uint2*)h4;
    }
    // hp full-H staging: 8b x 512h, slice0+slice1 (b1 pre-folded in slice 0).
    #pragma unroll
    for (int r = 0; r < 4; r++) {
        int idx = tid + r * 128;       // 0..511
        int b = idx >> 6, q = idx & 63;
        size_t off = (size_t)(b0 + b) * Hn + q * 8;
        uint4 x = *(const uint4*)(g_hp2 + off);
        uint4 y = *(const uint4*)(g_hp2 + Bn * Hn + off);
        uint4 z;
        z.x = hadd2u(x.x, y.x);  z.y = hadd2u(x.y, y.y);
        z.z = hadd2u(x.z, y.z);  z.w = hadd2u(x.w, y.w);
        *(uint4*)&hp_sh[b * HPP + q * 8] = z;
    }

    // cp.async staging map for hm chunks: 512 x 16B per chunk, 4 per thread.
    const unsigned hmU = (unsigned)__cvta_generic_to_shared(&hm_sh[0][0]);
    const unsigned hmBuf = 64 * 72 * 2;   // bytes per buffer
    const int svv = tid >> 3;             // v row 0..15 (+16 per r)
    const int sq8 = (tid & 7) * 8;        // h col (halves)

    auto stage_hm = [&](int ch) {
        int buf = ch & 1;
        int h0 = ch * 64;
        #pragma unroll
        for (int r = 0; r < 4; r++) {
            int vv = svv + r * 16;
            cp_async16(hmU + buf * hmBuf + (vv * 72 + sq8) * 2,
                       g_hm + (size_t)(v0 + vv) * Hn + h0 + sq8);
        }
        asm volatile("cp.async.commit_group;" ::: "memory");
    };

    float acc[8][4];
    #pragma unroll
    for (int b = 0; b < 8; b++)
        #pragma unroll
        for (int c = 0; c < 4; c++) acc[b][c] = 0.0f;

    stage_hm(0);
    stage_hm(1);

    for (int ch = 0; ch < 8; ch++) {
        if (ch < 7)
            asm volatile("cp.async.wait_group 1;" ::: "memory");
        else
            asm volatile("cp.async.wait_group 0;" ::: "memory");
        __syncthreads();

        const __half* hmb = hm_sh[ch & 1];
        const __half* hmr0 = &hmb[(vbase + g) * 72];
        const __half* hmr1 = &hmb[(vbase + g + 8) * 72];
        const int h0 = ch * 64;

        #pragma unroll
        for (int c = 0; c < 4; c++) {
            const int hb = c * 16;
            unsigned m00 = *(const unsigned*)&hmr0[hb + 2 * t];
            unsigned m10 = *(const unsigned*)&hmr1[hb + 2 * t];
            unsigned m01 = *(const unsigned*)&hmr0[hb + 2 * t + 8];
            unsigned m11 = *(const unsigned*)&hmr1[hb + 2 * t + 8];
            unsigned bw0 = *(const unsigned*)&w2h_sh[h0 + hb + 2 * t];
            unsigned bw1 = *(const unsigned*)&w2h_sh[h0 + hb + 2 * t + 8];
            #pragma unroll
            for (int b = 0; b < 8; b++) {
                const __half* hpr = &hp_sh[b * HPP + h0 + hb];
                unsigned p0 = *(const unsigned*)&hpr[2 * t];
                unsigned p1 = *(const unsigned*)&hpr[2 * t + 8];
                unsigned x0 = hadd2u(m00, p0);
                unsigned x1 = hadd2u(m10, p0);
                unsigned x2 = hadd2u(m01, p1);
                unsigned x3 = hadd2u(m11, p1);
                // Routing 11/32 on FMA pipe (a1 always; a3 for b<3).
                unsigned a0 = tanh2_f16(x0);
                unsigned a1 = tanh2_fma(x1);
                unsigned a2 = tanh2_f16(x2);
                unsigned a3 = (b < 3) ? tanh2_fma(x3) : tanh2_f16(x3);
                mma_16816(acc[b], a0, a1, a2, a3, bw0, bw1);
            }
        }
        __syncthreads();
        if (ch + 2 < 8) stage_hm(ch + 2);
    }

    const float b2 = *b2p;
    if (t == 0) {
        #pragma unroll
        for (int b = 0; b < 8; b++) {
            out[(size_t)(b0 + b) * Vn + v0 + vbase + g]     = acc[b][0] + b2;
            out[(size_t)(b0 + b) * Vn + v0 + vbase + g + 8] = acc[b][2] + b2;
        }
    }
}

extern "C" void kernel_launch(void* const* d_in, const int* in_sizes, int n_in,
                              void* d_out, int out_size) {
    const float* patient = (const float*)d_in[0];  // [B, PD]
    const float* atc4    = (const float*)d_in[1];  // [V, MD]
    const float* W1      = (const float*)d_in[2];  // [H, PD+MD]
    const float* b1      = (const float*)d_in[3];  // [H]
    const float* w2      = (const float*)d_in[4];  // [H]
    const float* b2      = (const float*)d_in[5];  // scalar
    float* out = (float*)d_out;                    // [B, V]

    hmma_gemm_kernel<<<80, 256>>>(patient, atc4, W1, b1);

    dim3 grid(Vn / 64, Bn / 8);    // 32 x 32 = 1024 blocks
    score_kernel<<<grid, 128>>>(w2, b2, out);
}

// round 15
// speedup vs baseline: 1.1236x; 1.0273x over previous
#include <cuda_runtime.h>
#include <cuda_fp16.h>
#include <cstdint>

#define Bn  256
#define Vn  2048
#define PDn 1024
#define MDn 512
#define Hn  512
#define W1LD (PDn + MDn)

#define GTP 40   // GEMM smem row stride (halves)
#define HPP 520  // score hp row stride (halves)

// Intermediates (device globals; no allocations).
__device__ __half g_hm[Vn * Hn];          // [v][h]
__device__ __half g_hp2[2 * Bn * Hn];     // split-K2 slices, [b][h]; b1 in slice 0

__device__ __forceinline__ unsigned tanh2_f16(unsigned x) {
    unsigned y;
    asm("tanh.approx.f16x2 %0, %1;" : "=r"(y) : "r"(x));
    return y;
}
__device__ __forceinline__ unsigned hadd2u(unsigned a, unsigned b) {
    unsigned d;
    asm("add.rn.f16x2 %0, %1, %2;" : "=r"(d) : "r"(a), "r"(b));
    return d;
}

// tanh on the FMA pipe (R10-proven): 12 f16x2 ops, no cvt/mov/div.
__device__ __forceinline__ unsigned tanh2_fma(unsigned xu) {
    __half2 x = *(__half2*)&xu;
    __half2 xc = __hmin2(__hmax2(x, __float2half2_rn(-2.75f)),
                         __float2half2_rn(2.75f));
    __half2 u = __hmul2(xc, xc);
    __half2 s = __hfma2(u, __float2half2_rn(0.26446280f),
                           __float2half2_rn(-1.0f));
    __half2 p = __hfma2(__float2half2_rn(-0.0224000f), s,
                        __float2half2_rn( 0.0371840f));
    p = __hfma2(p, s, __float2half2_rn(-0.0164160f));
    p = __hfma2(p, s, __float2half2_rn( 0.0272720f));
    p = __hfma2(p, s, __float2half2_rn(-0.0733200f));
    p = __hfma2(p, s, __float2half2_rn( 0.1221940f));
    p = __hfma2(p, s, __float2half2_rn(-0.2074220f));
    p = __hfma2(p, s, __float2half2_rn( 0.4935290f));
    __half2 y = __hmul2(xc, p);
    return *(unsigned*)&y;
}

__device__ __forceinline__ void mma_16816(float c[4],
    unsigned a0, unsigned a1, unsigned a2, unsigned a3,
    unsigned b0, unsigned b1)
{
    asm volatile(
        "mma.sync.aligned.m16n8k16.row.col.f32.f16.f16.f32 "
        "{%0,%1,%2,%3}, {%4,%5,%6,%7}, {%8,%9}, {%0,%1,%2,%3};"
        : "+f"(c[0]), "+f"(c[1]), "+f"(c[2]), "+f"(c[3])
        : "r"(a0), "r"(a1), "r"(a2), "r"(a3), "r"(b0), "r"(b1));
}
__device__ __forceinline__ void ldsm_x4(unsigned& r0, unsigned& r1,
                                        unsigned& r2, unsigned& r3,
                                        unsigned addr) {
    asm volatile("ldmatrix.sync.aligned.m8n8.x4.shared.b16 {%0,%1,%2,%3}, [%4];"
        : "=r"(r0), "=r"(r1), "=r"(r2), "=r"(r3) : "r"(addr));
}
__device__ __forceinline__ void cp_async16(unsigned smem, const void* gptr) {
    asm volatile("cp.async.cg.shared.global [%0], [%1], 16;"
        :: "r"(smem), "l"(gptr) : "memory");
}

// ---------------------------------------------------------------------------
// HMMA GEMM (R11 verbatim, measured ~10.7us). 80 blocks x 256 thr,
// tile 128m x 128h, K=512; ldmatrix fragments; double-buffered smem.
// ---------------------------------------------------------------------------
__global__ void __launch_bounds__(256) hmma_gemm_kernel(
    const float* __restrict__ patient,
    const float* __restrict__ atc4,
    const float* __restrict__ W1,
    const float* __restrict__ b1)
{
    __shared__ __half As[2][128 * GTP];
    __shared__ __half Ws[2][128 * GTP];

    const int bid = blockIdx.x;
    const int tid = threadIdx.x;

    const float* A;
    __half* dst;
    int LDA, m0, n0, kA0, kW0;
    bool add_b1;

    if (bid < 64) {                   // hm
        A = atc4;  LDA = MDn;  dst = g_hm;
        m0 = (bid & 15) * 128;
        n0 = (bid >> 4) * 128;
        kA0 = 0;  kW0 = PDn;
        add_b1 = false;
    } else {                          // hp split-K2
        int t = bid - 64;
        int s = t & 1;
        A = patient;  LDA = PDn;  dst = g_hp2 + s * (Bn * Hn);
        m0 = ((t >> 1) & 1) * 128;
        n0 = (t >> 2) * 128;
        kA0 = s * 512;  kW0 = s * 512;
        add_b1 = (s == 0);
    }

    const int wid = tid >> 5, lane = tid & 31;
    const int g = lane >> 2, t4 = lane & 3;
    const int wm = wid & 1, wn = wid >> 1;

    const int lrow = lane & 7;
    const int grp  = lane >> 3;
    const int baseA_h = (wm * 64 + lrow + (grp & 1) * 8) * GTP + (grp >> 1) * 8;
    const int baseB_h = (wn * 32 + lrow + (grp >> 1) * 8) * GTP + (grp & 1) * 8;

    const unsigned asU = (unsigned)__cvta_generic_to_shared(&As[0][0]);
    const unsigned wsU = (unsigned)__cvta_generic_to_shared(&Ws[0][0]);
    const unsigned bufStride = 128 * GTP * 2;

    float acc[4][4][4];
    #pragma unroll
    for (int i = 0; i < 4; i++)
        #pragma unroll
        for (int j = 0; j < 4; j++)
            #pragma unroll
            for (int c = 0; c < 4; c++) acc[i][j][c] = 0.0f;

    const int sr = tid >> 3;
    const int sq = tid & 7;

    float4 fA[4], fW[4];
    auto ldg = [&](int ch) {
        int k0 = ch * 32;
        #pragma unroll
        for (int it = 0; it < 4; it++) {
            int r = sr + it * 32;
            fA[it] = *(const float4*)(A  + (size_t)(m0 + r) * LDA  + kA0 + k0 + sq * 4);
            fW[it] = *(const float4*)(W1 + (size_t)(n0 + r) * W1LD + kW0 + k0 + sq * 4);
        }
    };
    auto sts = [&](int buf) {
        #pragma unroll
        for (int it = 0; it < 4; it++) {
            int r = sr + it * 32;
            __half ha[4] = { __float2half_rn(fA[it].x), __float2half_rn(fA[it].y),
                             __float2half_rn(fA[it].z), __float2half_rn(fA[it].w) };
            __half hw[4] = { __float2half_rn(fW[it].x), __float2half_rn(fW[it].y),
                             __float2half_rn(fW[it].z), __float2half_rn(fW[it].w) };
            *(uint2*)&As[buf][r * GTP + sq * 4] = *(uint2*)ha;
            *(uint2*)&Ws[buf][r * GTP + sq * 4] = *(uint2*)hw;
        }
    };

    const int NCH = 512 / 32;
    ldg(0);
    sts(0);
    ldg(1);
    __syncthreads();

    for (int c = 0; c < NCH; c++) {
        const int cur = c & 1;
        if (c + 1 < NCH) {
            sts(cur ^ 1);
            if (c + 2 < NCH) ldg(c + 2);
        }

        const unsigned aBase = asU + cur * bufStride + baseA_h * 2;
        const unsigned bBase = wsU + cur * bufStride + baseB_h * 2;

        #pragma unroll
        for (int ks = 0; ks < 2; ks++) {
            const int kOff = ks * 16 * 2;
            unsigned a[4][4], b[4][2];
            #pragma unroll
            for (int mi = 0; mi < 4; mi++)
                ldsm_x4(a[mi][0], a[mi][1], a[mi][2], a[mi][3],
                        aBase + mi * (16 * GTP * 2) + kOff);
            ldsm_x4(b[0][0], b[0][1], b[1][0], b[1][1], bBase + kOff);
            ldsm_x4(b[2][0], b[2][1], b[3][0], b[3][1],
                    bBase + 16 * GTP * 2 + kOff);
            #pragma unroll
            for (int mi = 0; mi < 4; mi++)
                #pragma unroll
                for (int j = 0; j < 4; j++)
                    mma_16816(acc[mi][j], a[mi][0], a[mi][1], a[mi][2], a[mi][3],
                              b[j][0], b[j][1]);
        }
        __syncthreads();
    }

    #pragma unroll
    for (int mi = 0; mi < 4; mi++) {
        int r0 = m0 + wm * 64 + mi * 16 + g, r1 = r0 + 8;
        #pragma unroll
        for (int j = 0; j < 4; j++) {
            int cn = n0 + wn * 32 + j * 8 + 2 * t4;
            float x0 = acc[mi][j][0], x1 = acc[mi][j][1];
            float x2 = acc[mi][j][2], x3 = acc[mi][j][3];
            if (add_b1) {
                float2 bb = *(const float2*)&b1[cn];
                x0 += bb.x; x1 += bb.y; x2 += bb.x; x3 += bb.y;
            }
            *(__half2*)&dst[(size_t)r0 * Hn + cn] = __floats2half2_rn(x0, x1);
            *(__half2*)&dst[(size_t)r1 * Hn + cn] = __floats2half2_rn(x2, x3);
        }
    }
}

// ---------------------------------------------------------------------------
// Score (R14 math verbatim; ONLY change: warp-private hm pipeline).
// Warp w stages AND reads exactly hm rows [16w, 16w+16) of each chunk ->
// buffers are row-disjoint across warps -> per-chunk __syncthreads removed;
// each warp runs cp.async.wait_group + __syncwarp independently (no convoy).
// One initial __syncthreads covers hp/w2. 64v x 8b tile, 128 thr, grid 1024.
// ---------------------------------------------------------------------------
__global__ void __launch_bounds__(128, 8) score_kernel(
    const float* __restrict__ w2, const float* __restrict__ b2p,
    float* __restrict__ out)
{
    __shared__ __half hm_sh[2][64 * 72];  // 18.4 KB double buffer
    __shared__ __half hp_sh[8 * HPP];     // 8.3 KB, full H per b
    __shared__ __half w2h_sh[Hn];

    const int tid  = threadIdx.x;
    const int v0   = blockIdx.x * 64;
    const int b0   = blockIdx.y * 8;
    const int lane = tid & 31;
    const int g    = lane >> 2;
    const int t    = lane & 3;
    const int warp = tid >> 5;
    const int vbase = warp * 16;

    {   // w2 -> fp16 once
        float4 w = ((const float4*)w2)[tid];
        __half h4[4] = { __float2half_rn(w.x), __float2half_rn(w.y),
                         __float2half_rn(w.z), __float2half_rn(w.w) };
        *(uint2*)&w2h_sh[tid * 4] = *(uint2*)h4;
    }
    // hp full-H staging: 8b x 512h, slice0+slice1 (b1 pre-folded in slice 0).
    #pragma unroll
    for (int r = 0; r < 4; r++) {
        int idx = tid + r * 128;       // 0..511
        int b = idx >> 6, q = idx & 63;
        size_t off = (size_t)(b0 + b) * Hn + q * 8;
        uint4 x = *(const uint4*)(g_hp2 + off);
        uint4 y = *(const uint4*)(g_hp2 + Bn * Hn + off);
        uint4 z;
        z.x = hadd2u(x.x, y.x);  z.y = hadd2u(x.y, y.y);
        z.z = hadd2u(x.z, y.z);  z.w = hadd2u(x.w, y.w);
        *(uint4*)&hp_sh[b * HPP + q * 8] = z;
    }

    // Warp-private cp.async staging: warp w stages rows [16w, 16w+16) only.
    // 16 rows x 8 segs(16B) = 128 segs / 32 lanes = 4 per lane.
    const unsigned hmU = (unsigned)__cvta_generic_to_shared(&hm_sh[0][0]);
    const unsigned hmBuf = 64 * 72 * 2;   // bytes per buffer
    const int srow = vbase + (lane >> 3); // + 4*r
    const int sq8  = (lane & 7) * 8;      // h col (halves)

    auto stage_hm = [&](int ch) {
        int buf = ch & 1;
        int h0 = ch * 64;
        #pragma unroll
        for (int r = 0; r < 4; r++) {
            int vv = srow + r * 4;
            cp_async16(hmU + buf * hmBuf + (vv * 72 + sq8) * 2,
                       g_hm + (size_t)(v0 + vv) * Hn + h0 + sq8);
        }
        asm volatile("cp.async.commit_group;" ::: "memory");
    };

    float acc[8][4];
    #pragma unroll
    for (int b = 0; b < 8; b++)
        #pragma unroll
        for (int c = 0; c < 4; c++) acc[b][c] = 0.0f;

    stage_hm(0);
    stage_hm(1);
    __syncthreads();   // hp + w2 visible to all warps (once)

    for (int ch = 0; ch < 8; ch++) {
        if (ch < 7)
            asm volatile("cp.async.wait_group 1;" ::: "memory");
        else
            asm volatile("cp.async.wait_group 0;" ::: "memory");
        __syncwarp();  // warp-local: own rows staged by own lanes only

        const __half* hmb = hm_sh[ch & 1];
        const __half* hmr0 = &hmb[(vbase + g) * 72];
        const __half* hmr1 = &hmb[(vbase + g + 8) * 72];
        const int h0 = ch * 64;

        #pragma unroll
        for (int c = 0; c < 4; c++) {
            const int hb = c * 16;
            unsigned m00 = *(const unsigned*)&hmr0[hb + 2 * t];
            unsigned m10 = *(const unsigned*)&hmr1[hb + 2 * t];
            unsigned m01 = *(const unsigned*)&hmr0[hb + 2 * t + 8];
            unsigned m11 = *(const unsigned*)&hmr1[hb + 2 * t + 8];
            unsigned bw0 = *(const unsigned*)&w2h_sh[h0 + hb + 2 * t];
            unsigned bw1 = *(const unsigned*)&w2h_sh[h0 + hb + 2 * t + 8];
            #pragma unroll
            for (int b = 0; b < 8; b++) {
                const __half* hpr = &hp_sh[b * HPP + h0 + hb];
                unsigned p0 = *(const unsigned*)&hpr[2 * t];
                unsigned p1 = *(const unsigned*)&hpr[2 * t + 8];
                unsigned x0 = hadd2u(m00, p0);
                unsigned x1 = hadd2u(m10, p0);
                unsigned x2 = hadd2u(m01, p1);
                unsigned x3 = hadd2u(m11, p1);
                // Routing 11/32 on FMA pipe (a1 always; a3 for b<3).
                unsigned a0 = tanh2_f16(x0);
                unsigned a1 = tanh2_fma(x1);
                unsigned a2 = tanh2_f16(x2);
                unsigned a3 = (b < 3) ? tanh2_fma(x3) : tanh2_f16(x3);
                mma_16816(acc[b], a0, a1, a2, a3, bw0, bw1);
            }
        }
        __syncwarp();  // warp done reading buf before re-staging it
        if (ch + 2 < 8) stage_hm(ch + 2);
    }

    const float b2 = *b2p;
    if (t == 0) {
        #pragma unroll
        for (int b = 0; b < 8; b++) {
            out[(size_t)(b0 + b) * Vn + v0 + vbase + g]     = acc[b][0] + b2;
            out[(size_t)(b0 + b) * Vn + v0 + vbase + g + 8] = acc[b][2] + b2;
        }
    }
}

extern "C" void kernel_launch(void* const* d_in, const int* in_sizes, int n_in,
                              void* d_out, int out_size) {
    const float* patient = (const float*)d_in[0];  // [B, PD]
    const float* atc4    = (const float*)d_in[1];  // [V, MD]
    const float* W1      = (const float*)d_in[2];  // [H, PD+MD]
    const float* b1      = (const float*)d_in[3];  // [H]
    const float* w2      = (const float*)d_in[4];  // [H]
    const float* b2      = (const float*)d_in[5];  // scalar
    float* out = (float*)d_out;                    // [B, V]

    hmma_gemm_kernel<<<80, 256>>>(patient, atc4, W1, b1);

    dim3 grid(Vn / 64, Bn / 8);    // 32 x 32 = 1024 blocks
    score_kernel<<<grid, 128>>>(w2, b2, out);
}